// round 11
// baseline (speedup 1.0000x reference)
#include <cuda_runtime.h>
#include <cuda_fp16.h>
#include <cstdint>

#define N_DIM 384
#define S_DIM 64
#define C_IN  64
#define C_H   32
#define C_OUT 128
#define LN_EPS 1e-5f

// ---------------- device scratch ----------------
__device__ __half g_A[N_DIM * C_H * S_DIM];      // [n][c][s] fp16
__device__ __half g_B[N_DIM * C_H * S_DIM];      // [n][d][s] fp16
__device__ __half g_W[16 * C_OUT * 64];          // [cidx][o][kk] fp16
__device__ unsigned long long g_mbits[N_DIM];

#define SWZ(b) ((b) ^ (((b) >> 3) & 0x70))

__device__ __forceinline__ uint32_t smem_u32(const void* p) {
    uint32_t a;
    asm("{ .reg .u64 t; cvta.to.shared.u64 t, %1; cvt.u32.u64 %0, t; }" : "=r"(a) : "l"(p));
    return a;
}
__device__ __forceinline__ void ldsm4(uint32_t r[4], uint32_t a) {
    asm volatile("ldmatrix.sync.aligned.m8n8.x4.shared.b16 {%0,%1,%2,%3}, [%4];"
                 : "=r"(r[0]), "=r"(r[1]), "=r"(r[2]), "=r"(r[3]) : "r"(a));
}
__device__ __forceinline__ void mma16816(float c[4], const uint32_t a[4], const uint32_t b[2]) {
    asm volatile("mma.sync.aligned.m16n8k16.row.col.f32.f16.f16.f32 "
                 "{%0,%1,%2,%3}, {%4,%5,%6,%7}, {%8,%9}, {%0,%1,%2,%3};"
                 : "+f"(c[0]), "+f"(c[1]), "+f"(c[2]), "+f"(c[3])
                 : "r"(a[0]), "r"(a[1]), "r"(a[2]), "r"(a[3]), "r"(b[0]), "r"(b[1]));
}
#define CP16(dst, src) asm volatile("cp.async.cg.shared.global [%0], [%1], 16;" :: "r"(dst), "l"(src))
#define CP_COMMIT()    asm volatile("cp.async.commit_group;" ::: "memory")
#define CP_WAIT(n)     asm volatile("cp.async.wait_group %0;" :: "n"(n) : "memory")

// ---------------------------------------------------------------------------
// fused prep + wo kernel (unchanged from R9).
//   blocks [0, 768):  prep for n = b>>1, s-half = b&1
//   blocks [768, 896): wo gather for o = b - 768
// ---------------------------------------------------------------------------
__global__ __launch_bounds__(512, 3) void prep_kernel(
    const float* __restrict__ m, const int* __restrict__ mask,
    const float* __restrict__ gamma, const float* __restrict__ beta,
    const float* __restrict__ Wa, const float* __restrict__ Wb,
    const float* __restrict__ Wo)
{
    __shared__ float sWa[C_H * 68];
    __shared__ float sWb[C_H * 68];
    __shared__ float sMn[16][C_IN];
    __shared__ __half sa[C_H * 34];
    __shared__ __half sb[C_H * 34];

    int tid = threadIdx.x, w = tid >> 5, l = tid & 31;
    int b = blockIdx.x;

    if (b >= 2 * N_DIM) {
        __shared__ float rowv[1024];
        int o = b - 2 * N_DIM;
        for (int i = tid; i < 1024; i += 512) rowv[i] = Wo[o * 1024 + i];
        __syncthreads();
        for (int r = tid; r < 1024; r += 512) {
            int cidx = r >> 6, kk = r & 63;
            int sl = cidx >> 2, ksub = cidx & 3;
            int c = sl * 8 + ksub * 2 + (kk >> 5), d = kk & 31;
            g_W[cidx * 8192 + o * 64 + kk] = __float2half(rowv[c * 32 + d]);
        }
        return;
    }

    int n = b >> 1, sh = b & 1;

    for (int i = tid; i < C_H * C_IN; i += 512) {
        int c = i >> 6, k = i & 63;
        sWa[c * 68 + k] = Wa[i];
        sWb[c * 68 + k] = Wb[i];
    }
    __syncthreads();

    float gam0 = gamma[l], gam1 = gamma[l + 32];
    float bet0 = beta[l],  bet1 = beta[l + 32];
    const float* wa = &sWa[l * 68];
    const float* wb = &sWb[l * 68];

    #pragma unroll
    for (int it = 0; it < 2; it++) {
        int sloc = it * 16 + w;
        int s = sh * 32 + sloc;
        int row = s * N_DIM + n;
        const float* mp = m + (size_t)row * C_IN;
        float v0 = mp[l], v1 = mp[l + 32];
        float sum = v0 + v1;
        #pragma unroll
        for (int o = 16; o; o >>= 1) sum += __shfl_xor_sync(0xffffffffu, sum, o);
        float mu = sum * (1.f / 64.f);
        float d0 = v0 - mu, d1 = v1 - mu;
        float sq = d0 * d0 + d1 * d1;
        #pragma unroll
        for (int o = 16; o; o >>= 1) sq += __shfl_xor_sync(0xffffffffu, sq, o);
        float inv = rsqrtf(sq * (1.f / 64.f) + LN_EPS);
        sMn[w][l]      = d0 * inv * gam0 + bet0;
        sMn[w][l + 32] = d1 * inv * gam1 + bet1;
        __syncwarp();
        float mf = (float)mask[row];
        float aa = 0.f, bb = 0.f;
        #pragma unroll
        for (int k4 = 0; k4 < 16; k4++) {
            float4 x  = *(const float4*)&sMn[w][k4 * 4];
            float4 A4 = *(const float4*)&wa[k4 * 4];
            float4 B4 = *(const float4*)&wb[k4 * 4];
            aa += x.x * A4.x + x.y * A4.y + x.z * A4.z + x.w * A4.w;
            bb += x.x * B4.x + x.y * B4.y + x.z * B4.z + x.w * B4.w;
        }
        sa[l * 34 + sloc] = __float2half(aa * mf);
        sb[l * 34 + sloc] = __float2half(bb * mf);
        __syncwarp();
    }
    __syncthreads();

    for (int e = tid; e < C_H * 32; e += 512) {
        int c = e >> 5, sloc = e & 31;
        size_t go = (size_t)n * 2048 + (size_t)c * 64 + sh * 32 + sloc;
        g_A[go] = sa[c * 34 + sloc];
        g_B[go] = sb[c * 34 + sloc];
    }

    if (sh == 0 && w == 0) {
        unsigned b0 = __ballot_sync(0xffffffffu, mask[l * N_DIM + n] != 0);
        unsigned b1 = __ballot_sync(0xffffffffu, mask[(l + 32) * N_DIM + n] != 0);
        if (l == 0) g_mbits[n] = (unsigned long long)b0 | ((unsigned long long)b1 << 32);
    }
}

// ---------------------------------------------------------------------------
// main: CTA = 8i x 8j = 64 pairs, 512 threads (16 warps, 4x4 warp grid).
// smem: As 32K | Bs 32K | Zs 32K | Wo 2x16K | invd
// ---------------------------------------------------------------------------
#define OFF_AS 0u
#define OFF_BS 32768u
#define OFF_ZS 65536u
#define OFF_WO 98304u
#define OFF_IV 131072u
#define SMEM_BYTES (131072 + 256)

__global__ void __launch_bounds__(512, 1) main_kernel(
    const float* __restrict__ bo, float* __restrict__ out)
{
    extern __shared__ char sm[];
    const uint32_t smb = smem_u32(sm);
    const int tid = threadIdx.x, wid = tid >> 5, lane = tid & 31;
    const int i0 = blockIdx.y * 8, j0 = blockIdx.x * 8;
    float* sInvd = (float*)(sm + OFF_IV);

    if (tid < 64) {
        unsigned long long wv = g_mbits[i0 + (tid >> 3)] & g_mbits[j0 + (tid & 7)];
        sInvd[tid] = 1.f / fmaxf((float)__popcll(wv), 1.f);
    }

    // prefetch Wo chunk 0 into buf0 (1024 uint4)
    {
        const char* src = (const char*)g_W;
        #pragma unroll
        for (int q = 0; q < 2; q++) {
            uint32_t rel = (uint32_t)(tid + q * 512) * 16u;
            CP16(smb + OFF_WO + SWZ(rel), src + rel);
        }
        CP_COMMIT();
    }

    // load A/B tiles (2048 uint4 each), swizzled
    {
        const char* srcA = (const char*)g_A + (size_t)i0 * 4096;
        const char* srcB = (const char*)g_B + (size_t)j0 * 4096;
        #pragma unroll
        for (int q = 0; q < 4; q++) {
            uint32_t rel = (uint32_t)(tid + q * 512) * 16u;
            uint32_t sw = SWZ(rel);
            *(uint4*)(sm + OFF_AS + sw) = *(const uint4*)(srcA + rel);
            *(uint4*)(sm + OFF_BS + sw) = *(const uint4*)(srcB + rel);
        }
    }
    __syncthreads();

    const int wm = wid >> 2, wn = wid & 3;   // 4x4 warp grid
    const int lr = lane & 15;
    const int lc = (lane >> 4) << 4;
    const int mrow = lane >> 2;
    const int ncol = (lane & 3) * 2;

    float acc2[4][4];                        // GEMM2: M16 x N32 per warp
    #pragma unroll
    for (int b = 0; b < 4; b++)
        #pragma unroll
        for (int c = 0; c < 4; c++) acc2[b][c] = 0.f;

    int cidx = 0;
    for (int sl = 0; sl < 4; sl++) {
        // ---- GEMM1 slice: M=64, N=256, K=64; warp tile M16 x N64 ----
        const int mb = wm * 16, nb = wn * 64;
        float acc1[8][4];
        #pragma unroll
        for (int b = 0; b < 8; b++)
            #pragma unroll
            for (int c = 0; c < 4; c++) acc1[b][c] = 0.f;

        #pragma unroll
        for (int k = 0; k < 4; k++) {
            uint32_t af[4];
            {
                int mm = mb + lr;
                int r = ((mm >> 3) << 5) + sl * 8 + (mm & 7);
                ldsm4(af, smb + OFF_AS + SWZ((uint32_t)(r * 128 + k * 32 + lc)));
            }
            uint32_t bf[8][2];
            #pragma unroll
            for (int tp = 0; tp < 4; tp++) {
                uint32_t q[4];
                int nn = nb + tp * 16 + lr;
                ldsm4(q, smb + OFF_BS + SWZ((uint32_t)(nn * 128 + k * 32 + lc)));
                bf[2*tp][0] = q[0]; bf[2*tp+1][0] = q[1];
                bf[2*tp][1] = q[2]; bf[2*tp+1][1] = q[3];
            }
            #pragma unroll
            for (int tn = 0; tn < 8; tn++)
                mma16816(acc1[tn], af, bf[tn]);
        }
        __syncthreads();   // S1: all warps done reading Zs (prev sl chunk 3)

        // ---- remap Z -> Zs[ksub][pair][kk] fp16 ----
        #pragma unroll
        for (int tn = 0; tn < 8; tn++) {
            int nn = nb + tn * 8 + ncol;
            int j = nn >> 5, d = nn & 31;
            #pragma unroll
            for (int h = 0; h < 2; h++) {
                int mm = mb + mrow + h * 8;
                int i = mm >> 3, cl = mm & 7;
                uint32_t rel = (uint32_t)((i * 8 + j) * 128 + ((cl & 1) * 32 + d) * 2);
                __half2 hv = __floats2half2_rn(acc1[tn][h*2], acc1[tn][h*2+1]);
                *(__half2*)(sm + OFF_ZS + (uint32_t)(cl >> 1) * 8192u + SWZ(rel)) = hv;
            }
        }
        __syncthreads();   // S2: remap visible

        // ---- GEMM2: 4 chunks; warp tile M16 x N32 ----
        const int pb = wm * 16, ob = wn * 32;
        for (int ksub = 0; ksub < 4; ksub++, cidx++) {
            CP_WAIT(0);        // W[cidx] landed
            __syncthreads();   // S3: visibility + buf[(cidx-1)&1] free

            if (cidx + 1 < 16) {
                const char* src = (const char*)g_W + (size_t)(cidx + 1) * 16384;
                uint32_t dst = smb + OFF_WO + (uint32_t)((cidx + 1) & 1) * 16384u;
                #pragma unroll
                for (int q = 0; q < 2; q++) {
                    uint32_t rel = (uint32_t)(tid + q * 512) * 16u;
                    CP16(dst + SWZ(rel), src + rel);
                }
                CP_COMMIT();
            }

            uint32_t zbase = smb + OFF_ZS + (uint32_t)ksub * 8192u;
            uint32_t wbase = smb + OFF_WO + (uint32_t)(cidx & 1) * 16384u;
            #pragma unroll
            for (int k = 0; k < 4; k++) {
                uint32_t af[4];
                {
                    int p = pb + lr;
                    ldsm4(af, zbase + SWZ((uint32_t)(p * 128 + k * 32 + lc)));
                }
                uint32_t bf[4][2];
                #pragma unroll
                for (int tp = 0; tp < 2; tp++) {
                    uint32_t q[4];
                    int o = ob + tp * 16 + lr;
                    ldsm4(q, wbase + SWZ((uint32_t)(o * 128 + k * 32 + lc)));
                    bf[2*tp][0] = q[0]; bf[2*tp+1][0] = q[1];
                    bf[2*tp][1] = q[2]; bf[2*tp+1][1] = q[3];
                }
                #pragma unroll
                for (int tn = 0; tn < 4; tn++)
                    mma16816(acc2[tn], af, bf[tn]);
            }
        }
    }

    // ---- epilogue: /denom, +bo, store ----
    const int pb = wm * 16, ob = wn * 32;
    float2 bo2[4];
    #pragma unroll
    for (int tn = 0; tn < 4; tn++)
        bo2[tn] = *(const float2*)(bo + ob + tn * 8 + ncol);

    #pragma unroll
    for (int h = 0; h < 2; h++) {
        int pair = pb + mrow + h * 8;
        int i = pair >> 3, j = pair & 7;
        float invd = sInvd[pair];
        float* op = out + ((size_t)(i0 + i) * N_DIM + (j0 + j)) * C_OUT;
        #pragma unroll
        for (int tn = 0; tn < 4; tn++) {
            float2 v;
            v.x = acc2[tn][h*2]   * invd + bo2[tn].x;
            v.y = acc2[tn][h*2+1] * invd + bo2[tn].y;
            *(float2*)(op + ob + tn * 8 + ncol) = v;
        }
    }
}

// ---------------------------------------------------------------------------
extern "C" void kernel_launch(void* const* d_in, const int* in_sizes, int n_in,
                              void* d_out, int out_size)
{
    const float* m     = (const float*)d_in[0];
    const int*   mask  = (const int*)  d_in[1];
    const float* gamma = (const float*)d_in[2];
    const float* beta  = (const float*)d_in[3];
    const float* Wa    = (const float*)d_in[4];
    const float* Wb    = (const float*)d_in[5];
    const float* Wo    = (const float*)d_in[6];
    const float* bo    = (const float*)d_in[7];
    float* out = (float*)d_out;

    cudaFuncSetAttribute(main_kernel, cudaFuncAttributeMaxDynamicSharedMemorySize, SMEM_BYTES);

    prep_kernel<<<2 * N_DIM + C_OUT, 512>>>(m, mask, gamma, beta, Wa, Wb, Wo);

    dim3 grid(N_DIM / 8, N_DIM / 8);
    main_kernel<<<grid, 512, SMEM_BYTES>>>(bo, out);
}

// round 12
// speedup vs baseline: 1.1431x; 1.1431x over previous
#include <cuda_runtime.h>
#include <cuda_fp16.h>
#include <cstdint>

#define N_DIM 384
#define S_DIM 64
#define C_IN  64
#define C_H   32
#define C_OUT 128
#define LN_EPS 1e-5f

// ---------------- device scratch ----------------
__device__ __half g_A[N_DIM * C_H * S_DIM];      // [n][c][s] fp16
__device__ __half g_B[N_DIM * C_H * S_DIM];      // [n][d][s] fp16
__device__ __half g_W[16 * C_OUT * 64];          // [cidx][o][kk] fp16
__device__ unsigned long long g_mbits[N_DIM];

#define SWZ(b) ((b) ^ (((b) >> 3) & 0x70))

__device__ __forceinline__ uint32_t smem_u32(const void* p) {
    uint32_t a;
    asm("{ .reg .u64 t; cvta.to.shared.u64 t, %1; cvt.u32.u64 %0, t; }" : "=r"(a) : "l"(p));
    return a;
}
__device__ __forceinline__ void ldsm4(uint32_t r[4], uint32_t a) {
    asm volatile("ldmatrix.sync.aligned.m8n8.x4.shared.b16 {%0,%1,%2,%3}, [%4];"
                 : "=r"(r[0]), "=r"(r[1]), "=r"(r[2]), "=r"(r[3]) : "r"(a));
}
__device__ __forceinline__ void mma16816(float c[4], const uint32_t a[4], const uint32_t b[2]) {
    asm volatile("mma.sync.aligned.m16n8k16.row.col.f32.f16.f16.f32 "
                 "{%0,%1,%2,%3}, {%4,%5,%6,%7}, {%8,%9}, {%0,%1,%2,%3};"
                 : "+f"(c[0]), "+f"(c[1]), "+f"(c[2]), "+f"(c[3])
                 : "r"(a[0]), "r"(a[1]), "r"(a[2]), "r"(a[3]), "r"(b[0]), "r"(b[1]));
}
#define CP16(dst, src) asm volatile("cp.async.cg.shared.global [%0], [%1], 16;" :: "r"(dst), "l"(src))
#define CP_COMMIT()    asm volatile("cp.async.commit_group;" ::: "memory")
#define CP_WAIT(n)     asm volatile("cp.async.wait_group %0;" :: "n"(n) : "memory")

// ---------------------------------------------------------------------------
// fused prep + wo kernel (unchanged from R9).
// ---------------------------------------------------------------------------
__global__ __launch_bounds__(512, 3) void prep_kernel(
    const float* __restrict__ m, const int* __restrict__ mask,
    const float* __restrict__ gamma, const float* __restrict__ beta,
    const float* __restrict__ Wa, const float* __restrict__ Wb,
    const float* __restrict__ Wo)
{
    __shared__ float sWa[C_H * 68];
    __shared__ float sWb[C_H * 68];
    __shared__ float sMn[16][C_IN];
    __shared__ __half sa[C_H * 34];
    __shared__ __half sb[C_H * 34];

    int tid = threadIdx.x, w = tid >> 5, l = tid & 31;
    int b = blockIdx.x;

    if (b >= 2 * N_DIM) {
        __shared__ float rowv[1024];
        int o = b - 2 * N_DIM;
        for (int i = tid; i < 1024; i += 512) rowv[i] = Wo[o * 1024 + i];
        __syncthreads();
        for (int r = tid; r < 1024; r += 512) {
            int cidx = r >> 6, kk = r & 63;
            int sl = cidx >> 2, ksub = cidx & 3;
            int c = sl * 8 + ksub * 2 + (kk >> 5), d = kk & 31;
            g_W[cidx * 8192 + o * 64 + kk] = __float2half(rowv[c * 32 + d]);
        }
        return;
    }

    int n = b >> 1, sh = b & 1;

    for (int i = tid; i < C_H * C_IN; i += 512) {
        int c = i >> 6, k = i & 63;
        sWa[c * 68 + k] = Wa[i];
        sWb[c * 68 + k] = Wb[i];
    }
    __syncthreads();

    float gam0 = gamma[l], gam1 = gamma[l + 32];
    float bet0 = beta[l],  bet1 = beta[l + 32];
    const float* wa = &sWa[l * 68];
    const float* wb = &sWb[l * 68];

    #pragma unroll
    for (int it = 0; it < 2; it++) {
        int sloc = it * 16 + w;
        int s = sh * 32 + sloc;
        int row = s * N_DIM + n;
        const float* mp = m + (size_t)row * C_IN;
        float v0 = mp[l], v1 = mp[l + 32];
        float sum = v0 + v1;
        #pragma unroll
        for (int o = 16; o; o >>= 1) sum += __shfl_xor_sync(0xffffffffu, sum, o);
        float mu = sum * (1.f / 64.f);
        float d0 = v0 - mu, d1 = v1 - mu;
        float sq = d0 * d0 + d1 * d1;
        #pragma unroll
        for (int o = 16; o; o >>= 1) sq += __shfl_xor_sync(0xffffffffu, sq, o);
        float inv = rsqrtf(sq * (1.f / 64.f) + LN_EPS);
        sMn[w][l]      = d0 * inv * gam0 + bet0;
        sMn[w][l + 32] = d1 * inv * gam1 + bet1;
        __syncwarp();
        float mf = (float)mask[row];
        float aa = 0.f, bb = 0.f;
        #pragma unroll
        for (int k4 = 0; k4 < 16; k4++) {
            float4 x  = *(const float4*)&sMn[w][k4 * 4];
            float4 A4 = *(const float4*)&wa[k4 * 4];
            float4 B4 = *(const float4*)&wb[k4 * 4];
            aa += x.x * A4.x + x.y * A4.y + x.z * A4.z + x.w * A4.w;
            bb += x.x * B4.x + x.y * B4.y + x.z * B4.z + x.w * B4.w;
        }
        sa[l * 34 + sloc] = __float2half(aa * mf);
        sb[l * 34 + sloc] = __float2half(bb * mf);
        __syncwarp();
    }
    __syncthreads();

    for (int e = tid; e < C_H * 32; e += 512) {
        int c = e >> 5, sloc = e & 31;
        size_t go = (size_t)n * 2048 + (size_t)c * 64 + sh * 32 + sloc;
        g_A[go] = sa[c * 34 + sloc];
        g_B[go] = sb[c * 34 + sloc];
    }

    if (sh == 0 && w == 0) {
        unsigned b0 = __ballot_sync(0xffffffffu, mask[l * N_DIM + n] != 0);
        unsigned b1 = __ballot_sync(0xffffffffu, mask[(l + 32) * N_DIM + n] != 0);
        if (l == 0) g_mbits[n] = (unsigned long long)b0 | ((unsigned long long)b1 << 32);
    }
}

// ---------------------------------------------------------------------------
// main: CTA = 8i x 8j = 64 pairs, 256 threads (R4 tiling).
// Wo staged per-slice: 4 buffers (64KB), one cp.async group per slice.
// Barriers: 2 per slice. smem: As 32K | Bs 32K | Zs 32K | Wo 4x16K | invd
// ---------------------------------------------------------------------------
#define OFF_AS 0u
#define OFF_BS 32768u
#define OFF_ZS 65536u
#define OFF_WO 98304u
#define OFF_IV 163840u
#define SMEM_BYTES (163840 + 256)

__global__ void __launch_bounds__(256, 1) main_kernel(
    const float* __restrict__ bo, float* __restrict__ out)
{
    extern __shared__ char sm[];
    const uint32_t smb = smem_u32(sm);
    const int tid = threadIdx.x, wid = tid >> 5, lane = tid & 31;
    const int i0 = blockIdx.y * 8, j0 = blockIdx.x * 8;
    float* sInvd = (float*)(sm + OFF_IV);

    if (tid < 64) {
        unsigned long long wv = g_mbits[i0 + (tid >> 3)] & g_mbits[j0 + (tid & 7)];
        sInvd[tid] = 1.f / fmaxf((float)__popcll(wv), 1.f);
    }

    // prefetch all 4 Wo chunks of slice 0 (one group)
    {
        #pragma unroll
        for (int ks = 0; ks < 4; ks++) {
            const char* src = (const char*)g_W + (size_t)ks * 16384;
            uint32_t dst = smb + OFF_WO + (uint32_t)ks * 16384u;
            #pragma unroll
            for (int q = 0; q < 4; q++) {
                uint32_t rel = (uint32_t)(tid + q * 256) * 16u;
                CP16(dst + SWZ(rel), src + rel);
            }
        }
        CP_COMMIT();
    }

    // load A/B tiles (256 rows x 128B each, contiguous), swizzled
    {
        const char* srcA = (const char*)g_A + (size_t)i0 * 4096;
        const char* srcB = (const char*)g_B + (size_t)j0 * 4096;
        #pragma unroll
        for (int q = 0; q < 8; q++) {
            uint32_t rel = (uint32_t)(tid + q * 256) * 16u;
            uint32_t sw = SWZ(rel);
            *(uint4*)(sm + OFF_AS + sw) = *(const uint4*)(srcA + rel);
            *(uint4*)(sm + OFF_BS + sw) = *(const uint4*)(srcB + rel);
        }
    }
    __syncthreads();   // As/Bs + sInvd visible

    const int wm = wid >> 2, wn = wid & 3;
    const int lr = lane & 15;
    const int lc = (lane >> 4) << 4;
    const int mrow = lane >> 2;
    const int ncol = (lane & 3) * 2;

    float acc2[2][4][4];
    #pragma unroll
    for (int a = 0; a < 2; a++)
        #pragma unroll
        for (int b = 0; b < 4; b++)
            #pragma unroll
            for (int c = 0; c < 4; c++) acc2[a][b][c] = 0.f;

    for (int sl = 0; sl < 4; sl++) {
        // ---- GEMM1 slice: M=64 ((i,c_l)), N=256 ((j,d)), K=64 (s), fp32 acc ----
        const int mb = wm * 32, nb = wn * 64;
        float acc1[2][8][4];
        #pragma unroll
        for (int a = 0; a < 2; a++)
            #pragma unroll
            for (int b = 0; b < 8; b++)
                #pragma unroll
                for (int c = 0; c < 4; c++) acc1[a][b][c] = 0.f;

        #pragma unroll
        for (int k = 0; k < 4; k++) {
            uint32_t af[2][4];
            #pragma unroll
            for (int tm = 0; tm < 2; tm++) {
                int mm = mb + tm * 16 + lr;
                int r = ((mm >> 3) << 5) + sl * 8 + (mm & 7);
                ldsm4(af[tm], smb + OFF_AS + SWZ((uint32_t)(r * 128 + k * 32 + lc)));
            }
            uint32_t bf[8][2];
            #pragma unroll
            for (int tp = 0; tp < 4; tp++) {
                uint32_t q[4];
                int nn = nb + tp * 16 + lr;
                ldsm4(q, smb + OFF_BS + SWZ((uint32_t)(nn * 128 + k * 32 + lc)));
                bf[2*tp][0] = q[0]; bf[2*tp+1][0] = q[1];
                bf[2*tp][1] = q[2]; bf[2*tp+1][1] = q[3];
            }
            #pragma unroll
            for (int tm = 0; tm < 2; tm++)
                #pragma unroll
                for (int tn = 0; tn < 8; tn++)
                    mma16816(acc1[tm][tn], af[tm], bf[tn]);
        }

        // ---- remap Z -> Zs[ksub][pair][kk] fp16 (safe: S_end of prev slice) ----
        #pragma unroll
        for (int tm = 0; tm < 2; tm++) {
            #pragma unroll
            for (int tn = 0; tn < 8; tn++) {
                int nn = nb + tn * 8 + ncol;
                int j = nn >> 5, d = nn & 31;
                #pragma unroll
                for (int h = 0; h < 2; h++) {
                    int mm = mb + tm * 16 + mrow + h * 8;
                    int i = mm >> 3, cl = mm & 7;
                    uint32_t rel = (uint32_t)((i * 8 + j) * 128 + ((cl & 1) * 32 + d) * 2);
                    __half2 hv = __floats2half2_rn(acc1[tm][tn][h*2], acc1[tm][tn][h*2+1]);
                    *(__half2*)(sm + OFF_ZS + (uint32_t)(cl >> 1) * 8192u + SWZ(rel)) = hv;
                }
            }
        }

        CP_WAIT(0);        // this slice's 4 Wo chunks landed (own issues)
        __syncthreads();   // S2: remap + Wo visible to all warps

        // ---- GEMM2: 4 chunks back-to-back, NO barriers ----
        const int pb = wm * 32, ob = wn * 32;
        #pragma unroll
        for (int ksub = 0; ksub < 4; ksub++) {
            uint32_t zbase = smb + OFF_ZS + (uint32_t)ksub * 8192u;
            uint32_t wbase = smb + OFF_WO + (uint32_t)ksub * 16384u;
            #pragma unroll
            for (int k = 0; k < 4; k++) {
                uint32_t af[2][4];
                #pragma unroll
                for (int tm = 0; tm < 2; tm++) {
                    int p = pb + tm * 16 + lr;
                    ldsm4(af[tm], zbase + SWZ((uint32_t)(p * 128 + k * 32 + lc)));
                }
                uint32_t bf[4][2];
                #pragma unroll
                for (int tp = 0; tp < 2; tp++) {
                    uint32_t q[4];
                    int o = ob + tp * 16 + lr;
                    ldsm4(q, wbase + SWZ((uint32_t)(o * 128 + k * 32 + lc)));
                    bf[2*tp][0] = q[0]; bf[2*tp+1][0] = q[1];
                    bf[2*tp][1] = q[2]; bf[2*tp+1][1] = q[3];
                }
                #pragma unroll
                for (int tm = 0; tm < 2; tm++)
                    #pragma unroll
                    for (int tn = 0; tn < 4; tn++)
                        mma16816(acc2[tm][tn], af[tm], bf[tn]);
            }
        }

        if (sl + 1 < 4) {
            __syncthreads();   // S_end: all warps done reading Wo bufs + Zs
            // issue next slice's 4 Wo chunks (streams under next GEMM1+remap)
            #pragma unroll
            for (int ks = 0; ks < 4; ks++) {
                const char* src = (const char*)g_W + (size_t)((sl + 1) * 4 + ks) * 16384;
                uint32_t dst = smb + OFF_WO + (uint32_t)ks * 16384u;
                #pragma unroll
                for (int q = 0; q < 4; q++) {
                    uint32_t rel = (uint32_t)(tid + q * 256) * 16u;
                    CP16(dst + SWZ(rel), src + rel);
                }
            }
            CP_COMMIT();
        }
    }

    // ---- epilogue: /denom, +bo, store ----
    const int pb = wm * 32, ob = wn * 32;
    float2 bo2[4];
    #pragma unroll
    for (int tn = 0; tn < 4; tn++)
        bo2[tn] = *(const float2*)(bo + ob + tn * 8 + ncol);

    #pragma unroll
    for (int tm = 0; tm < 2; tm++) {
        #pragma unroll
        for (int h = 0; h < 2; h++) {
            int pair = pb + tm * 16 + mrow + h * 8;
            int i = pair >> 3, j = pair & 7;
            float invd = sInvd[pair];
            float* op = out + ((size_t)(i0 + i) * N_DIM + (j0 + j)) * C_OUT;
            #pragma unroll
            for (int tn = 0; tn < 4; tn++) {
                float2 v;
                v.x = acc2[tm][tn][h*2]   * invd + bo2[tn].x;
                v.y = acc2[tm][tn][h*2+1] * invd + bo2[tn].y;
                *(float2*)(op + ob + tn * 8 + ncol) = v;
            }
        }
    }
}

// ---------------------------------------------------------------------------
extern "C" void kernel_launch(void* const* d_in, const int* in_sizes, int n_in,
                              void* d_out, int out_size)
{
    const float* m     = (const float*)d_in[0];
    const int*   mask  = (const int*)  d_in[1];
    const float* gamma = (const float*)d_in[2];
    const float* beta  = (const float*)d_in[3];
    const float* Wa    = (const float*)d_in[4];
    const float* Wb    = (const float*)d_in[5];
    const float* Wo    = (const float*)d_in[6];
    const float* bo    = (const float*)d_in[7];
    float* out = (float*)d_out;

    cudaFuncSetAttribute(main_kernel, cudaFuncAttributeMaxDynamicSharedMemorySize, SMEM_BYTES);

    prep_kernel<<<2 * N_DIM + C_OUT, 512>>>(m, mask, gamma, beta, Wa, Wb, Wo);

    dim3 grid(N_DIM / 8, N_DIM / 8);
    main_kernel<<<grid, 256, SMEM_BYTES>>>(bo, out);
}

// round 14
// speedup vs baseline: 1.2575x; 1.1000x over previous
#include <cuda_runtime.h>
#include <cuda_fp16.h>
#include <cstdint>

#define N_DIM 384
#define S_DIM 64
#define C_IN  64
#define C_H   32
#define C_OUT 128
#define LN_EPS 1e-5f

// ---------------- device scratch ----------------
__device__ __half g_A[N_DIM * C_H * S_DIM];      // [n][c][s] fp16
__device__ __half g_B[N_DIM * C_H * S_DIM];      // [n][d][s] fp16
__device__ __half g_W[16 * C_OUT * 64];          // [cidx][o][kk] fp16
__device__ unsigned long long g_mbits[N_DIM];

#define SWZ(b) ((b) ^ (((b) >> 3) & 0x70))

__device__ __forceinline__ uint32_t smem_u32(const void* p) {
    uint32_t a;
    asm("{ .reg .u64 t; cvta.to.shared.u64 t, %1; cvt.u32.u64 %0, t; }" : "=r"(a) : "l"(p));
    return a;
}
__device__ __forceinline__ void ldsm4(uint32_t r[4], uint32_t a) {
    asm volatile("ldmatrix.sync.aligned.m8n8.x4.shared.b16 {%0,%1,%2,%3}, [%4];"
                 : "=r"(r[0]), "=r"(r[1]), "=r"(r[2]), "=r"(r[3]) : "r"(a));
}
__device__ __forceinline__ void mma16816(float c[4], const uint32_t a[4], const uint32_t b[2]) {
    asm volatile("mma.sync.aligned.m16n8k16.row.col.f32.f16.f16.f32 "
                 "{%0,%1,%2,%3}, {%4,%5,%6,%7}, {%8,%9}, {%0,%1,%2,%3};"
                 : "+f"(c[0]), "+f"(c[1]), "+f"(c[2]), "+f"(c[3])
                 : "r"(a[0]), "r"(a[1]), "r"(a[2]), "r"(a[3]), "r"(b[0]), "r"(b[1]));
}
#define CP16(dst, src) asm volatile("cp.async.cg.shared.global [%0], [%1], 16;" :: "r"(dst), "l"(src))
#define CP_COMMIT()    asm volatile("cp.async.commit_group;" ::: "memory")
#define CP_WAIT(n)     asm volatile("cp.async.wait_group %0;" :: "n"(n) : "memory")

// ---------------------------------------------------------------------------
// fused prep + wo kernel (unchanged).
// ---------------------------------------------------------------------------
__global__ __launch_bounds__(512, 3) void prep_kernel(
    const float* __restrict__ m, const int* __restrict__ mask,
    const float* __restrict__ gamma, const float* __restrict__ beta,
    const float* __restrict__ Wa, const float* __restrict__ Wb,
    const float* __restrict__ Wo)
{
    __shared__ float sWa[C_H * 68];
    __shared__ float sWb[C_H * 68];
    __shared__ float sMn[16][C_IN];
    __shared__ __half sa[C_H * 34];
    __shared__ __half sb[C_H * 34];

    int tid = threadIdx.x, w = tid >> 5, l = tid & 31;
    int b = blockIdx.x;

    if (b >= 2 * N_DIM) {
        __shared__ float rowv[1024];
        int o = b - 2 * N_DIM;
        for (int i = tid; i < 1024; i += 512) rowv[i] = Wo[o * 1024 + i];
        __syncthreads();
        for (int r = tid; r < 1024; r += 512) {
            int cidx = r >> 6, kk = r & 63;
            int sl = cidx >> 2, ksub = cidx & 3;
            int c = sl * 8 + ksub * 2 + (kk >> 5), d = kk & 31;
            g_W[cidx * 8192 + o * 64 + kk] = __float2half(rowv[c * 32 + d]);
        }
        return;
    }

    int n = b >> 1, sh = b & 1;

    for (int i = tid; i < C_H * C_IN; i += 512) {
        int c = i >> 6, k = i & 63;
        sWa[c * 68 + k] = Wa[i];
        sWb[c * 68 + k] = Wb[i];
    }
    __syncthreads();

    float gam0 = gamma[l], gam1 = gamma[l + 32];
    float bet0 = beta[l],  bet1 = beta[l + 32];
    const float* wa = &sWa[l * 68];
    const float* wb = &sWb[l * 68];

    #pragma unroll
    for (int it = 0; it < 2; it++) {
        int sloc = it * 16 + w;
        int s = sh * 32 + sloc;
        int row = s * N_DIM + n;
        const float* mp = m + (size_t)row * C_IN;
        float v0 = mp[l], v1 = mp[l + 32];
        float sum = v0 + v1;
        #pragma unroll
        for (int o = 16; o; o >>= 1) sum += __shfl_xor_sync(0xffffffffu, sum, o);
        float mu = sum * (1.f / 64.f);
        float d0 = v0 - mu, d1 = v1 - mu;
        float sq = d0 * d0 + d1 * d1;
        #pragma unroll
        for (int o = 16; o; o >>= 1) sq += __shfl_xor_sync(0xffffffffu, sq, o);
        float inv = rsqrtf(sq * (1.f / 64.f) + LN_EPS);
        sMn[w][l]      = d0 * inv * gam0 + bet0;
        sMn[w][l + 32] = d1 * inv * gam1 + bet1;
        __syncwarp();
        float mf = (float)mask[row];
        float aa = 0.f, bb = 0.f;
        #pragma unroll
        for (int k4 = 0; k4 < 16; k4++) {
            float4 x  = *(const float4*)&sMn[w][k4 * 4];
            float4 A4 = *(const float4*)&wa[k4 * 4];
            float4 B4 = *(const float4*)&wb[k4 * 4];
            aa += x.x * A4.x + x.y * A4.y + x.z * A4.z + x.w * A4.w;
            bb += x.x * B4.x + x.y * B4.y + x.z * B4.z + x.w * B4.w;
        }
        sa[l * 34 + sloc] = __float2half(aa * mf);
        sb[l * 34 + sloc] = __float2half(bb * mf);
        __syncwarp();
    }
    __syncthreads();

    for (int e = tid; e < C_H * 32; e += 512) {
        int c = e >> 5, sloc = e & 31;
        size_t go = (size_t)n * 2048 + (size_t)c * 64 + sh * 32 + sloc;
        g_A[go] = sa[c * 34 + sloc];
        g_B[go] = sb[c * 34 + sloc];
    }

    if (sh == 0 && w == 0) {
        unsigned b0 = __ballot_sync(0xffffffffu, mask[l * N_DIM + n] != 0);
        unsigned b1 = __ballot_sync(0xffffffffu, mask[(l + 32) * N_DIM + n] != 0);
        if (l == 0) g_mbits[n] = (unsigned long long)b0 | ((unsigned long long)b1 << 32);
    }
}

// ---------------------------------------------------------------------------
// main: CTA = 8i x 8j = 64 pairs, 256 threads.
// Zs uses a ksub-XOR bank rotation (conflict-free remap STS).
// GEMM2 runs the 16 (ksub,k) steps software-pipelined, no barriers.
// smem: As 32K | Bs 32K | Zs 32K | Wo 4x16K | invd
// ---------------------------------------------------------------------------
#define OFF_AS 0u
#define OFF_BS 32768u
#define OFF_ZS 65536u
#define OFF_WO 98304u
#define OFF_IV 163840u
#define SMEM_BYTES (163840 + 256)

// Zs smem OFFSET: ksub buffer + SW128 row swizzle + ksub bank-rotation.
// Used identically on the write (remap) and read (GEMM2 ldsm) sides.
#define ZOFF(ks, rel) (OFF_ZS + (uint32_t)(ks) * 8192u + (SWZ((uint32_t)(rel)) ^ ((uint32_t)(ks) << 4)))

__global__ void __launch_bounds__(256, 1) main_kernel(
    const float* __restrict__ bo, float* __restrict__ out)
{
    extern __shared__ char sm[];
    const uint32_t smb = smem_u32(sm);
    const int tid = threadIdx.x, wid = tid >> 5, lane = tid & 31;
    const int i0 = blockIdx.y * 8, j0 = blockIdx.x * 8;
    float* sInvd = (float*)(sm + OFF_IV);

    if (tid < 64) {
        unsigned long long wv = g_mbits[i0 + (tid >> 3)] & g_mbits[j0 + (tid & 7)];
        sInvd[tid] = 1.f / fmaxf((float)__popcll(wv), 1.f);
    }

    // prefetch all 4 Wo chunks of slice 0 (one group)
    {
        #pragma unroll
        for (int ks = 0; ks < 4; ks++) {
            const char* src = (const char*)g_W + (size_t)ks * 16384;
            uint32_t dst = smb + OFF_WO + (uint32_t)ks * 16384u;
            #pragma unroll
            for (int q = 0; q < 4; q++) {
                uint32_t rel = (uint32_t)(tid + q * 256) * 16u;
                CP16(dst + SWZ(rel), src + rel);
            }
        }
        CP_COMMIT();
    }

    // load A/B tiles (256 rows x 128B each, contiguous), swizzled
    {
        const char* srcA = (const char*)g_A + (size_t)i0 * 4096;
        const char* srcB = (const char*)g_B + (size_t)j0 * 4096;
        #pragma unroll
        for (int q = 0; q < 8; q++) {
            uint32_t rel = (uint32_t)(tid + q * 256) * 16u;
            uint32_t sw = SWZ(rel);
            *(uint4*)(sm + OFF_AS + sw) = *(const uint4*)(srcA + rel);
            *(uint4*)(sm + OFF_BS + sw) = *(const uint4*)(srcB + rel);
        }
    }
    __syncthreads();   // As/Bs + sInvd visible

    const int wm = wid >> 2, wn = wid & 3;
    const int lr = lane & 15;
    const int lc = (lane >> 4) << 4;
    const int mrow = lane >> 2;
    const int ncol = (lane & 3) * 2;

    float acc2[2][4][4];
    #pragma unroll
    for (int a = 0; a < 2; a++)
        #pragma unroll
        for (int b = 0; b < 4; b++)
            #pragma unroll
            for (int c = 0; c < 4; c++) acc2[a][b][c] = 0.f;

    const int pb = wm * 32, ob = wn * 32;

    for (int sl = 0; sl < 4; sl++) {
        // ---- GEMM1 slice: M=64 ((i,c_l)), N=256 ((j,d)), K=64 (s), fp32 acc ----
        const int mb = wm * 32, nb = wn * 64;
        float acc1[2][8][4];
        #pragma unroll
        for (int a = 0; a < 2; a++)
            #pragma unroll
            for (int b = 0; b < 8; b++)
                #pragma unroll
                for (int c = 0; c < 4; c++) acc1[a][b][c] = 0.f;

        #pragma unroll
        for (int k = 0; k < 4; k++) {
            uint32_t af[2][4];
            #pragma unroll
            for (int tm = 0; tm < 2; tm++) {
                int mm = mb + tm * 16 + lr;
                int r = ((mm >> 3) << 5) + sl * 8 + (mm & 7);
                ldsm4(af[tm], smb + OFF_AS + SWZ((uint32_t)(r * 128 + k * 32 + lc)));
            }
            uint32_t bf[8][2];
            #pragma unroll
            for (int tp = 0; tp < 4; tp++) {
                uint32_t q[4];
                int nn = nb + tp * 16 + lr;
                ldsm4(q, smb + OFF_BS + SWZ((uint32_t)(nn * 128 + k * 32 + lc)));
                bf[2*tp][0] = q[0]; bf[2*tp+1][0] = q[1];
                bf[2*tp][1] = q[2]; bf[2*tp+1][1] = q[3];
            }
            #pragma unroll
            for (int tm = 0; tm < 2; tm++)
                #pragma unroll
                for (int tn = 0; tn < 8; tn++)
                    mma16816(acc1[tm][tn], af[tm], bf[tn]);
        }

        // ---- remap Z -> Zs (ksub-rotated swizzle: conflict-free) ----
        #pragma unroll
        for (int tm = 0; tm < 2; tm++) {
            #pragma unroll
            for (int tn = 0; tn < 8; tn++) {
                int nn = nb + tn * 8 + ncol;
                int j = nn >> 5, d = nn & 31;
                #pragma unroll
                for (int h = 0; h < 2; h++) {
                    int mm = mb + tm * 16 + mrow + h * 8;
                    int i = mm >> 3, cl = mm & 7;
                    uint32_t rel = (uint32_t)((i * 8 + j) * 128 + ((cl & 1) * 32 + d) * 2);
                    __half2 hv = __floats2half2_rn(acc1[tm][tn][h*2], acc1[tm][tn][h*2+1]);
                    *(__half2*)(sm + ZOFF(cl >> 1, rel)) = hv;
                }
            }
        }

        CP_WAIT(0);        // this slice's 4 Wo chunks landed
        __syncthreads();   // S2: remap + Wo visible to all warps

        // ---- GEMM2: 16 steps (ksub,k), software-pipelined, no barriers ----
        {
            uint32_t af[2][2][4];   // [buf][tm][4]
            uint32_t bf[2][4][2];   // [buf][tn][2]

            // preload step 0
            #pragma unroll
            for (int tm = 0; tm < 2; tm++) {
                int p = pb + tm * 16 + lr;
                ldsm4(af[0][tm], smb + ZOFF(0, p * 128 + lc));
            }
            #pragma unroll
            for (int tp = 0; tp < 2; tp++) {
                uint32_t q[4];
                int o = ob + tp * 16 + lr;
                ldsm4(q, smb + OFF_WO + SWZ((uint32_t)(o * 128 + lc)));
                bf[0][2*tp][0] = q[0]; bf[0][2*tp+1][0] = q[1];
                bf[0][2*tp][1] = q[2]; bf[0][2*tp+1][1] = q[3];
            }

            #pragma unroll
            for (int t = 0; t < 16; t++) {
                const int cur = t & 1, nxt = cur ^ 1;
                if (t < 15) {
                    const int tt = t + 1;
                    const int ks = tt >> 2, k = tt & 3;
                    #pragma unroll
                    for (int tm = 0; tm < 2; tm++) {
                        int p = pb + tm * 16 + lr;
                        ldsm4(af[nxt][tm], smb + ZOFF(ks, p * 128 + k * 32 + lc));
                    }
                    uint32_t wbase = smb + OFF_WO + (uint32_t)ks * 16384u;
                    #pragma unroll
                    for (int tp = 0; tp < 2; tp++) {
                        uint32_t q[4];
                        int o = ob + tp * 16 + lr;
                        ldsm4(q, wbase + SWZ((uint32_t)(o * 128 + k * 32 + lc)));
                        bf[nxt][2*tp][0] = q[0]; bf[nxt][2*tp+1][0] = q[1];
                        bf[nxt][2*tp][1] = q[2]; bf[nxt][2*tp+1][1] = q[3];
                    }
                }
                #pragma unroll
                for (int tm = 0; tm < 2; tm++)
                    #pragma unroll
                    for (int tn = 0; tn < 4; tn++)
                        mma16816(acc2[tm][tn], af[cur][tm], bf[cur][tn]);
            }
        }

        if (sl + 1 < 4) {
            __syncthreads();   // S_end: all warps done reading Wo bufs + Zs
            #pragma unroll
            for (int ks = 0; ks < 4; ks++) {
                const char* src = (const char*)g_W + (size_t)((sl + 1) * 4 + ks) * 16384;
                uint32_t dst = smb + OFF_WO + (uint32_t)ks * 16384u;
                #pragma unroll
                for (int q = 0; q < 4; q++) {
                    uint32_t rel = (uint32_t)(tid + q * 256) * 16u;
                    CP16(dst + SWZ(rel), src + rel);
                }
            }
            CP_COMMIT();
        }
    }

    // ---- epilogue: /denom, +bo, store ----
    float2 bo2[4];
    #pragma unroll
    for (int tn = 0; tn < 4; tn++)
        bo2[tn] = *(const float2*)(bo + ob + tn * 8 + ncol);

    #pragma unroll
    for (int tm = 0; tm < 2; tm++) {
        #pragma unroll
        for (int h = 0; h < 2; h++) {
            int pair = pb + tm * 16 + mrow + h * 8;
            int i = pair >> 3, j = pair & 7;
            float invd = sInvd[pair];
            float* op = out + ((size_t)(i0 + i) * N_DIM + (j0 + j)) * C_OUT;
            #pragma unroll
            for (int tn = 0; tn < 4; tn++) {
                float2 v;
                v.x = acc2[tm][tn][h*2]   * invd + bo2[tn].x;
                v.y = acc2[tm][tn][h*2+1] * invd + bo2[tn].y;
                *(float2*)(op + ob + tn * 8 + ncol) = v;
            }
        }
    }
}

// ---------------------------------------------------------------------------
extern "C" void kernel_launch(void* const* d_in, const int* in_sizes, int n_in,
                              void* d_out, int out_size)
{
    const float* m     = (const float*)d_in[0];
    const int*   mask  = (const int*)  d_in[1];
    const float* gamma = (const float*)d_in[2];
    const float* beta  = (const float*)d_in[3];
    const float* Wa    = (const float*)d_in[4];
    const float* Wb    = (const float*)d_in[5];
    const float* Wo    = (const float*)d_in[6];
    const float* bo    = (const float*)d_in[7];
    float* out = (float*)d_out;

    cudaFuncSetAttribute(main_kernel, cudaFuncAttributeMaxDynamicSharedMemorySize, SMEM_BYTES);

    prep_kernel<<<2 * N_DIM + C_OUT, 512>>>(m, mask, gamma, beta, Wa, Wb, Wo);

    dim3 grid(N_DIM / 8, N_DIM / 8);
    main_kernel<<<grid, 256, SMEM_BYTES>>>(bo, out);
}

// round 15
// speedup vs baseline: 1.2594x; 1.0015x over previous
#include <cuda_runtime.h>
#include <cuda_fp16.h>
#include <cstdint>

#define N_DIM 384
#define S_DIM 64
#define C_IN  64
#define C_H   32
#define C_OUT 128
#define LN_EPS 1e-5f

// ---------------- device scratch ----------------
__device__ __half g_A[N_DIM * C_H * S_DIM];      // [n][c][s] fp16
__device__ __half g_B[N_DIM * C_H * S_DIM];      // [n][d][s] fp16
__device__ __half g_W[16 * C_OUT * 64];          // [cidx][o][kk] fp16
__device__ unsigned long long g_mbits[N_DIM];

#define SWZ(b) ((b) ^ (((b) >> 3) & 0x70))

__device__ __forceinline__ uint32_t smem_u32(const void* p) {
    uint32_t a;
    asm("{ .reg .u64 t; cvta.to.shared.u64 t, %1; cvt.u32.u64 %0, t; }" : "=r"(a) : "l"(p));
    return a;
}
__device__ __forceinline__ void ldsm4(uint32_t r[4], uint32_t a) {
    asm volatile("ldmatrix.sync.aligned.m8n8.x4.shared.b16 {%0,%1,%2,%3}, [%4];"
                 : "=r"(r[0]), "=r"(r[1]), "=r"(r[2]), "=r"(r[3]) : "r"(a));
}
__device__ __forceinline__ void mma16816(float c[4], const uint32_t a[4], const uint32_t b[2]) {
    asm volatile("mma.sync.aligned.m16n8k16.row.col.f32.f16.f16.f32 "
                 "{%0,%1,%2,%3}, {%4,%5,%6,%7}, {%8,%9}, {%0,%1,%2,%3};"
                 : "+f"(c[0]), "+f"(c[1]), "+f"(c[2]), "+f"(c[3])
                 : "r"(a[0]), "r"(a[1]), "r"(a[2]), "r"(a[3]), "r"(b[0]), "r"(b[1]));
}
#define CP16(dst, src) asm volatile("cp.async.cg.shared.global [%0], [%1], 16;" :: "r"(dst), "l"(src))
#define CP_COMMIT()    asm volatile("cp.async.commit_group;" ::: "memory")
#define CP_WAIT(n)     asm volatile("cp.async.wait_group %0;" :: "n"(n) : "memory")

// ---------------------------------------------------------------------------
// fused prep + wo kernel (unchanged).
// ---------------------------------------------------------------------------
__global__ __launch_bounds__(512, 3) void prep_kernel(
    const float* __restrict__ m, const int* __restrict__ mask,
    const float* __restrict__ gamma, const float* __restrict__ beta,
    const float* __restrict__ Wa, const float* __restrict__ Wb,
    const float* __restrict__ Wo)
{
    __shared__ float sWa[C_H * 68];
    __shared__ float sWb[C_H * 68];
    __shared__ float sMn[16][C_IN];
    __shared__ __half sa[C_H * 34];
    __shared__ __half sb[C_H * 34];

    int tid = threadIdx.x, w = tid >> 5, l = tid & 31;
    int b = blockIdx.x;

    if (b >= 2 * N_DIM) {
        __shared__ float rowv[1024];
        int o = b - 2 * N_DIM;
        for (int i = tid; i < 1024; i += 512) rowv[i] = Wo[o * 1024 + i];
        __syncthreads();
        for (int r = tid; r < 1024; r += 512) {
            int cidx = r >> 6, kk = r & 63;
            int sl = cidx >> 2, ksub = cidx & 3;
            int c = sl * 8 + ksub * 2 + (kk >> 5), d = kk & 31;
            g_W[cidx * 8192 + o * 64 + kk] = __float2half(rowv[c * 32 + d]);
        }
        return;
    }

    int n = b >> 1, sh = b & 1;

    for (int i = tid; i < C_H * C_IN; i += 512) {
        int c = i >> 6, k = i & 63;
        sWa[c * 68 + k] = Wa[i];
        sWb[c * 68 + k] = Wb[i];
    }
    __syncthreads();

    float gam0 = gamma[l], gam1 = gamma[l + 32];
    float bet0 = beta[l],  bet1 = beta[l + 32];
    const float* wa = &sWa[l * 68];
    const float* wb = &sWb[l * 68];

    #pragma unroll
    for (int it = 0; it < 2; it++) {
        int sloc = it * 16 + w;
        int s = sh * 32 + sloc;
        int row = s * N_DIM + n;
        const float* mp = m + (size_t)row * C_IN;
        float v0 = mp[l], v1 = mp[l + 32];
        float sum = v0 + v1;
        #pragma unroll
        for (int o = 16; o; o >>= 1) sum += __shfl_xor_sync(0xffffffffu, sum, o);
        float mu = sum * (1.f / 64.f);
        float d0 = v0 - mu, d1 = v1 - mu;
        float sq = d0 * d0 + d1 * d1;
        #pragma unroll
        for (int o = 16; o; o >>= 1) sq += __shfl_xor_sync(0xffffffffu, sq, o);
        float inv = rsqrtf(sq * (1.f / 64.f) + LN_EPS);
        sMn[w][l]      = d0 * inv * gam0 + bet0;
        sMn[w][l + 32] = d1 * inv * gam1 + bet1;
        __syncwarp();
        float mf = (float)mask[row];
        float aa = 0.f, bb = 0.f;
        #pragma unroll
        for (int k4 = 0; k4 < 16; k4++) {
            float4 x  = *(const float4*)&sMn[w][k4 * 4];
            float4 A4 = *(const float4*)&wa[k4 * 4];
            float4 B4 = *(const float4*)&wb[k4 * 4];
            aa += x.x * A4.x + x.y * A4.y + x.z * A4.z + x.w * A4.w;
            bb += x.x * B4.x + x.y * B4.y + x.z * B4.z + x.w * B4.w;
        }
        sa[l * 34 + sloc] = __float2half(aa * mf);
        sb[l * 34 + sloc] = __float2half(bb * mf);
        __syncwarp();
    }
    __syncthreads();

    for (int e = tid; e < C_H * 32; e += 512) {
        int c = e >> 5, sloc = e & 31;
        size_t go = (size_t)n * 2048 + (size_t)c * 64 + sh * 32 + sloc;
        g_A[go] = sa[c * 34 + sloc];
        g_B[go] = sb[c * 34 + sloc];
    }

    if (sh == 0 && w == 0) {
        unsigned b0 = __ballot_sync(0xffffffffu, mask[l * N_DIM + n] != 0);
        unsigned b1 = __ballot_sync(0xffffffffu, mask[(l + 32) * N_DIM + n] != 0);
        if (l == 0) g_mbits[n] = (unsigned long long)b0 | ((unsigned long long)b1 << 32);
    }
}

// ---------------------------------------------------------------------------
// main: CTA = 8i x 8j = 64 pairs, 256 threads.
// GEMM1 and GEMM2 both software-pipelined with double-buffered fragments.
// Zs ksub-XOR bank rotation. smem: As 32K | Bs 32K | Zs 32K | Wo 4x16K | iv
// ---------------------------------------------------------------------------
#define OFF_AS 0u
#define OFF_BS 32768u
#define OFF_ZS 65536u
#define OFF_WO 98304u
#define OFF_IV 163840u
#define SMEM_BYTES (163840 + 256)

#define ZOFF(ks, rel) (OFF_ZS + (uint32_t)(ks) * 8192u + (SWZ((uint32_t)(rel)) ^ ((uint32_t)(ks) << 4)))

__global__ void __launch_bounds__(256, 1) main_kernel(
    const float* __restrict__ bo, float* __restrict__ out)
{
    extern __shared__ char sm[];
    const uint32_t smb = smem_u32(sm);
    const int tid = threadIdx.x, wid = tid >> 5, lane = tid & 31;
    const int i0 = blockIdx.y * 8, j0 = blockIdx.x * 8;
    float* sInvd = (float*)(sm + OFF_IV);

    if (tid < 64) {
        unsigned long long wv = g_mbits[i0 + (tid >> 3)] & g_mbits[j0 + (tid & 7)];
        sInvd[tid] = 1.f / fmaxf((float)__popcll(wv), 1.f);
    }

    // prefetch all 4 Wo chunks of slice 0 (one group)
    {
        #pragma unroll
        for (int ks = 0; ks < 4; ks++) {
            const char* src = (const char*)g_W + (size_t)ks * 16384;
            uint32_t dst = smb + OFF_WO + (uint32_t)ks * 16384u;
            #pragma unroll
            for (int q = 0; q < 4; q++) {
                uint32_t rel = (uint32_t)(tid + q * 256) * 16u;
                CP16(dst + SWZ(rel), src + rel);
            }
        }
        CP_COMMIT();
    }

    // load A/B tiles, swizzled
    {
        const char* srcA = (const char*)g_A + (size_t)i0 * 4096;
        const char* srcB = (const char*)g_B + (size_t)j0 * 4096;
        #pragma unroll
        for (int q = 0; q < 8; q++) {
            uint32_t rel = (uint32_t)(tid + q * 256) * 16u;
            uint32_t sw = SWZ(rel);
            *(uint4*)(sm + OFF_AS + sw) = *(const uint4*)(srcA + rel);
            *(uint4*)(sm + OFF_BS + sw) = *(const uint4*)(srcB + rel);
        }
    }
    __syncthreads();

    const int wm = wid >> 2, wn = wid & 3;
    const int lr = lane & 15;
    const int lc = (lane >> 4) << 4;
    const int mrow = lane >> 2;
    const int ncol = (lane & 3) * 2;

    float acc2[2][4][4];
    #pragma unroll
    for (int a = 0; a < 2; a++)
        #pragma unroll
        for (int b = 0; b < 4; b++)
            #pragma unroll
            for (int c = 0; c < 4; c++) acc2[a][b][c] = 0.f;

    const int pb = wm * 32, ob = wn * 32;
    const int mb = wm * 32, nb = wn * 64;

    for (int sl = 0; sl < 4; sl++) {
        // ---- GEMM1 slice: M=64, N=256, K=64; software-pipelined k-loop ----
        float acc1[2][8][4];
        #pragma unroll
        for (int a = 0; a < 2; a++)
            #pragma unroll
            for (int b = 0; b < 8; b++)
                #pragma unroll
                for (int c = 0; c < 4; c++) acc1[a][b][c] = 0.f;

        {
            uint32_t af[2][2][4];   // [buf][tm][4]
            uint32_t bf[2][8][2];   // [buf][tn][2]

            // preload k=0
            #pragma unroll
            for (int tm = 0; tm < 2; tm++) {
                int mm = mb + tm * 16 + lr;
                int r = ((mm >> 3) << 5) + sl * 8 + (mm & 7);
                ldsm4(af[0][tm], smb + OFF_AS + SWZ((uint32_t)(r * 128 + lc)));
            }
            #pragma unroll
            for (int tp = 0; tp < 4; tp++) {
                uint32_t q[4];
                int nn = nb + tp * 16 + lr;
                ldsm4(q, smb + OFF_BS + SWZ((uint32_t)(nn * 128 + lc)));
                bf[0][2*tp][0] = q[0]; bf[0][2*tp+1][0] = q[1];
                bf[0][2*tp][1] = q[2]; bf[0][2*tp+1][1] = q[3];
            }

            #pragma unroll
            for (int k = 0; k < 4; k++) {
                const int cur = k & 1, nxt = cur ^ 1;
                if (k < 3) {
                    const int kk = k + 1;
                    #pragma unroll
                    for (int tm = 0; tm < 2; tm++) {
                        int mm = mb + tm * 16 + lr;
                        int r = ((mm >> 3) << 5) + sl * 8 + (mm & 7);
                        ldsm4(af[nxt][tm], smb + OFF_AS + SWZ((uint32_t)(r * 128 + kk * 32 + lc)));
                    }
                    #pragma unroll
                    for (int tp = 0; tp < 4; tp++) {
                        uint32_t q[4];
                        int nn = nb + tp * 16 + lr;
                        ldsm4(q, smb + OFF_BS + SWZ((uint32_t)(nn * 128 + kk * 32 + lc)));
                        bf[nxt][2*tp][0] = q[0]; bf[nxt][2*tp+1][0] = q[1];
                        bf[nxt][2*tp][1] = q[2]; bf[nxt][2*tp+1][1] = q[3];
                    }
                }
                #pragma unroll
                for (int tm = 0; tm < 2; tm++)
                    #pragma unroll
                    for (int tn = 0; tn < 8; tn++)
                        mma16816(acc1[tm][tn], af[cur][tm], bf[cur][tn]);
            }
        }

        // ---- remap Z -> Zs (ksub-rotated swizzle) ----
        #pragma unroll
        for (int tm = 0; tm < 2; tm++) {
            #pragma unroll
            for (int tn = 0; tn < 8; tn++) {
                int nn = nb + tn * 8 + ncol;
                int j = nn >> 5, d = nn & 31;
                #pragma unroll
                for (int h = 0; h < 2; h++) {
                    int mm = mb + tm * 16 + mrow + h * 8;
                    int i = mm >> 3, cl = mm & 7;
                    uint32_t rel = (uint32_t)((i * 8 + j) * 128 + ((cl & 1) * 32 + d) * 2);
                    __half2 hv = __floats2half2_rn(acc1[tm][tn][h*2], acc1[tm][tn][h*2+1]);
                    *(__half2*)(sm + ZOFF(cl >> 1, rel)) = hv;
                }
            }
        }

        CP_WAIT(0);        // this slice's 4 Wo chunks landed
        __syncthreads();   // S2: remap + Wo visible

        // ---- GEMM2: 16 steps (ksub,k), software-pipelined ----
        {
            uint32_t af[2][2][4];
            uint32_t bf[2][4][2];

            #pragma unroll
            for (int tm = 0; tm < 2; tm++) {
                int p = pb + tm * 16 + lr;
                ldsm4(af[0][tm], smb + ZOFF(0, p * 128 + lc));
            }
            #pragma unroll
            for (int tp = 0; tp < 2; tp++) {
                uint32_t q[4];
                int o = ob + tp * 16 + lr;
                ldsm4(q, smb + OFF_WO + SWZ((uint32_t)(o * 128 + lc)));
                bf[0][2*tp][0] = q[0]; bf[0][2*tp+1][0] = q[1];
                bf[0][2*tp][1] = q[2]; bf[0][2*tp+1][1] = q[3];
            }

            #pragma unroll
            for (int t = 0; t < 16; t++) {
                const int cur = t & 1, nxt = cur ^ 1;
                if (t < 15) {
                    const int tt = t + 1;
                    const int ks = tt >> 2, k = tt & 3;
                    #pragma unroll
                    for (int tm = 0; tm < 2; tm++) {
                        int p = pb + tm * 16 + lr;
                        ldsm4(af[nxt][tm], smb + ZOFF(ks, p * 128 + k * 32 + lc));
                    }
                    uint32_t wbase = smb + OFF_WO + (uint32_t)ks * 16384u;
                    #pragma unroll
                    for (int tp = 0; tp < 2; tp++) {
                        uint32_t q[4];
                        int o = ob + tp * 16 + lr;
                        ldsm4(q, wbase + SWZ((uint32_t)(o * 128 + k * 32 + lc)));
                        bf[nxt][2*tp][0] = q[0]; bf[nxt][2*tp+1][0] = q[1];
                        bf[nxt][2*tp][1] = q[2]; bf[nxt][2*tp+1][1] = q[3];
                    }
                }
                #pragma unroll
                for (int tm = 0; tm < 2; tm++)
                    #pragma unroll
                    for (int tn = 0; tn < 4; tn++)
                        mma16816(acc2[tm][tn], af[cur][tm], bf[cur][tn]);
            }
        }

        if (sl + 1 < 4) {
            __syncthreads();   // S_end: Wo bufs + Zs free
            #pragma unroll
            for (int ks = 0; ks < 4; ks++) {
                const char* src = (const char*)g_W + (size_t)((sl + 1) * 4 + ks) * 16384;
                uint32_t dst = smb + OFF_WO + (uint32_t)ks * 16384u;
                #pragma unroll
                for (int q = 0; q < 4; q++) {
                    uint32_t rel = (uint32_t)(tid + q * 256) * 16u;
                    CP16(dst + SWZ(rel), src + rel);
                }
            }
            CP_COMMIT();
        }
    }

    // ---- epilogue: /denom, +bo, store ----
    float2 bo2[4];
    #pragma unroll
    for (int tn = 0; tn < 4; tn++)
        bo2[tn] = *(const float2*)(bo + ob + tn * 8 + ncol);

    #pragma unroll
    for (int tm = 0; tm < 2; tm++) {
        #pragma unroll
        for (int h = 0; h < 2; h++) {
            int pair = pb + tm * 16 + mrow + h * 8;
            int i = pair >> 3, j = pair & 7;
            float invd = sInvd[pair];
            float* op = out + ((size_t)(i0 + i) * N_DIM + (j0 + j)) * C_OUT;
            #pragma unroll
            for (int tn = 0; tn < 4; tn++) {
                float2 v;
                v.x = acc2[tm][tn][h*2]   * invd + bo2[tn].x;
                v.y = acc2[tm][tn][h*2+1] * invd + bo2[tn].y;
                *(float2*)(op + ob + tn * 8 + ncol) = v;
            }
        }
    }
}

// ---------------------------------------------------------------------------
extern "C" void kernel_launch(void* const* d_in, const int* in_sizes, int n_in,
                              void* d_out, int out_size)
{
    const float* m     = (const float*)d_in[0];
    const int*   mask  = (const int*)  d_in[1];
    const float* gamma = (const float*)d_in[2];
    const float* beta  = (const float*)d_in[3];
    const float* Wa    = (const float*)d_in[4];
    const float* Wb    = (const float*)d_in[5];
    const float* Wo    = (const float*)d_in[6];
    const float* bo    = (const float*)d_in[7];
    float* out = (float*)d_out;

    cudaFuncSetAttribute(main_kernel, cudaFuncAttributeMaxDynamicSharedMemorySize, SMEM_BYTES);

    prep_kernel<<<2 * N_DIM + C_OUT, 512>>>(m, mask, gamma, beta, Wa, Wb, Wo);

    dim3 grid(N_DIM / 8, N_DIM / 8);
    main_kernel<<<grid, 256, SMEM_BYTES>>>(bo, out);
}